// round 1
// baseline (speedup 1.0000x reference)
#include <cuda_runtime.h>
#include <math.h>

// ---------------- problem constants (fixed for this instance) ----------------
static constexpr int Bn  = 4;
static constexpr int C   = 256;
static constexpr int S3  = 128, S4 = 64, S5 = 32;
static constexpr int N3  = S3*S3*3;          // 49152
static constexpr int N4  = S4*S4*3;          // 12288
static constexpr int N5  = S5*S5*3;          // 3072
static constexpr int NTOT = N3 + N4 + N5;    // 64512
static constexpr int PRE  = 400;
static constexpr int POST = 100;
static constexpr float NMS_T  = 0.7f;
static constexpr float IMGW   = 1024.0f;     // S3 * stride_p3
static constexpr float IMGH   = 1024.0f;
#define SCLAMP 3.3322045101752038f           // log(224/8) cast to f32

// ---------------- device scratch (static, allocation-free) ----------------
__device__ float g_wt[9*256*256];     // [pos][cin][cout]
__device__ float g_wh[16*256];        // head weights: rows 0..2 obj, 3..14 box, 15 zero
__device__ float g_bh[16];
__device__ float g_scores[Bn*NTOT];
__device__ float g_boxes [Bn*NTOT*4];
__device__ float g_tboxes[12*PRE*4];  // top-400 boxes per (level,b)

// ---------------- weight prep ----------------
__global__ void prep_stem_w(const float* __restrict__ w) {
    int i = blockIdx.x * 256 + threadIdx.x;
    if (i < 9*256*256) {
        int pos  = i >> 16;          // /65536
        int cin  = (i >> 8) & 255;
        int cout = i & 255;
        g_wt[i] = w[(cout*256 + cin)*9 + pos];
    }
}

__global__ void prep_head(const float* __restrict__ wobj, const float* __restrict__ bobj,
                          const float* __restrict__ wbox, const float* __restrict__ bbox) {
    int i = blockIdx.x * 256 + threadIdx.x;
    if (i < 16*256) {
        int o = i >> 8, k = i & 255;
        float v = 0.f;
        if (o < 3)        v = wobj[o*256 + k];
        else if (o < 15)  v = wbox[(o-3)*256 + k];
        g_wh[i] = v;
    }
    if (i < 16) {
        float v = 0.f;
        if (i < 3)        v = bobj[i];
        else if (i < 15)  v = bbox[i-3];
        g_bh[i] = v;
    }
}

// ---------------- fused stem conv + head + decode ----------------
// tile: M=256 couts x N=64 pixels, 256 threads, thread tile 8x8.
// K loop: 9 positions x 32 chunks of 8 cins = 288 steps, double-buffered smem.
static constexpr int CONV_SMEM = (256*65 + 16*256 + 16*65) * 4;  // 87104 B (epilogue is the max)

__global__ __launch_bounds__(256, 2)
void conv_head_kernel(const float* __restrict__ f3, const float* __restrict__ f4,
                      const float* __restrict__ f5, const float* __restrict__ bstem) {
    extern __shared__ float sm[];
    float* As = sm;                 // [2][8][256]
    float* Bs = sm + 2*8*256;       // [2][8][64]
    float* st = sm;                 // epilogue alias: stem [256][65]
    float* wh = sm + 256*65;        //                 head w [16][256]
    float* hs = sm + 256*65 + 16*256; //               head out [16][65]

    int t = blockIdx.x;
    int level, b, tile, S, logS, stride, loff;
    const float* feat;
    if (t < 1024)      { level=0; b=t>>8; tile=t&255; S=128; logS=7; stride=8;  feat=f3; loff=0;      }
    else if (t < 1280) { t-=1024; level=1; b=t>>6; tile=t&63; S=64;  logS=6; stride=16; feat=f4; loff=N3;     }
    else               { t-=1280; level=2; b=t>>4; tile=t&15; S=32;  logS=5; stride=32; feat=f5; loff=N3+N4;  }
    (void)level;

    const int tid = threadIdx.x;
    const int m0  = (tid >> 3) * 8;
    const int n0  = (tid & 7) * 8;
    const int p0  = tile * 64;
    const int nb  = tid & 63;        // B-tile pixel this thread loads
    const int kb0 = tid >> 6;        // 0..3
    const int pix = p0 + nb;
    const int ph  = pix >> logS;
    const int pw  = pix & (S - 1);
    const int SS2 = logS + logS;

    float acc[8][8];
    #pragma unroll
    for (int i = 0; i < 8; i++)
        #pragma unroll
        for (int j = 0; j < 8; j++) acc[i][j] = 0.f;

    float ra[8], rb[2];
    auto load_step = [&](int s) {
        int pos = s >> 5;
        int c0  = (s & 31) << 3;
        const float* wrow = g_wt + (pos << 16) + (c0 << 8) + tid;
        #pragma unroll
        for (int i = 0; i < 8; i++) ra[i] = wrow[i << 8];
        int kh = pos / 3;
        int dh = kh - 1, dw = pos - kh*3 - 1;
        int y = ph + dh, x = pw + dw;
        rb[0] = 0.f; rb[1] = 0.f;
        if ((unsigned)y < (unsigned)S && (unsigned)x < (unsigned)S) {
            const float* fb = feat + (((b << 8) + c0 + kb0) << SS2) + (y << logS) + x;
            rb[0] = fb[0];
            rb[1] = fb[4 << SS2];
        }
    };

    load_step(0);
    for (int s = 0; s < 288; s++) {
        int buf = s & 1;
        __syncthreads();
        {
            float* Aw = As + buf*8*256;
            float* Bw = Bs + buf*8*64;
            #pragma unroll
            for (int i = 0; i < 8; i++) Aw[i*256 + tid] = ra[i];
            Bw[kb0*64 + nb]     = rb[0];
            Bw[(kb0+4)*64 + nb] = rb[1];
        }
        __syncthreads();
        if (s + 1 < 288) load_step(s + 1);
        const float* Ak = As + buf*8*256;
        const float* Bk = Bs + buf*8*64;
        #pragma unroll
        for (int k = 0; k < 8; k++) {
            float a[8], bb[8];
            #pragma unroll
            for (int i = 0; i < 8; i++) a[i]  = Ak[k*256 + m0 + i];
            #pragma unroll
            for (int j = 0; j < 8; j++) bb[j] = Bk[k*64  + n0 + j];
            #pragma unroll
            for (int i = 0; i < 8; i++)
                #pragma unroll
                for (int j = 0; j < 8; j++)
                    acc[i][j] = fmaf(a[i], bb[j], acc[i][j]);
        }
    }
    __syncthreads();   // done with As/Bs; smem re-used below

    // bias + relu, stash stem tile
    #pragma unroll
    for (int i = 0; i < 8; i++) {
        float bsv = bstem[m0 + i];
        #pragma unroll
        for (int j = 0; j < 8; j++) {
            float v = fmaxf(acc[i][j] + bsv, 0.f);
            st[(m0 + i)*65 + (n0 + j)] = v;
        }
    }
    for (int i = tid; i < 16*256; i += 256) wh[i] = g_wh[i];
    __syncthreads();

    // head GEMM: 15(+1 pad) x 64 from smem
    {
        int og = tid >> 6;       // 0..3 -> head rows og*4..og*4+3
        int n  = tid & 63;
        float h0 = 0.f, h1 = 0.f, h2 = 0.f, h3 = 0.f;
        const float* w0 = wh + (og*4 + 0)*256;
        const float* w1 = wh + (og*4 + 1)*256;
        const float* w2 = wh + (og*4 + 2)*256;
        const float* w3 = wh + (og*4 + 3)*256;
        #pragma unroll 4
        for (int k = 0; k < 256; k++) {
            float sv = st[k*65 + n];
            h0 = fmaf(w0[k], sv, h0);
            h1 = fmaf(w1[k], sv, h1);
            h2 = fmaf(w2[k], sv, h2);
            h3 = fmaf(w3[k], sv, h3);
        }
        hs[(og*4 + 0)*65 + n] = h0 + g_bh[og*4 + 0];
        hs[(og*4 + 1)*65 + n] = h1 + g_bh[og*4 + 1];
        hs[(og*4 + 2)*65 + n] = h2 + g_bh[og*4 + 2];
        hs[(og*4 + 3)*65 + n] = h3 + g_bh[og*4 + 3];
    }
    __syncthreads();

    // decode anchors + deltas, clip, write scores/boxes
    if (tid < 192) {
        int n = tid / 3;
        int a = tid - n*3;
        int pixel = p0 + n;
        int hh = pixel >> logS, ww = pixel & (S - 1);
        float sF   = (float)stride;
        float side = 8.0f * sF;
        float area = side * side;
        float arat = (a == 0) ? 0.5f : (a == 1 ? 1.0f : 2.0f);
        float wsz  = sqrtf(area / arat);
        float hsz  = area / wsz;
        float xc = (ww + 0.5f) * sF, yc = (hh + 0.5f) * sF;
        float x1 = xc - wsz*0.5f, x2 = xc + wsz*0.5f;
        float y1 = yc - hsz*0.5f, y2 = yc + hsz*0.5f;
        float aw = x2 - x1, ah = y2 - y1;
        float acx = x1 + 0.5f*aw, acy = y1 + 0.5f*ah;

        float dx = hs[(3 + a*4 + 0)*65 + n];
        float dy = hs[(3 + a*4 + 1)*65 + n];
        float dw = fminf(hs[(3 + a*4 + 2)*65 + n], SCLAMP);
        float dh = fminf(hs[(3 + a*4 + 3)*65 + n], SCLAMP);
        float pcx = dx*aw + acx, pcy = dy*ah + acy;
        float pwd = expf(dw)*aw, phd = expf(dh)*ah;
        float bx1 = fminf(fmaxf(pcx - 0.5f*pwd, 0.f), IMGW);
        float by1 = fminf(fmaxf(pcy - 0.5f*phd, 0.f), IMGH);
        float bx2 = fminf(fmaxf(pcx + 0.5f*pwd, 0.f), IMGW);
        float by2 = fminf(fmaxf(pcy + 0.5f*phd, 0.f), IMGH);

        int gi = b*NTOT + loff + pixel*3 + a;
        g_scores[gi] = hs[a*65 + n];
        *(float4*)(g_boxes + (size_t)gi*4) = make_float4(bx1, by1, bx2, by2);
    }
}

// ---------------- top-400 per (level,b): radix histogram + bitonic ----------------
__device__ __forceinline__ unsigned f2o(float f) {
    unsigned u = __float_as_uint(f);
    return (u & 0x80000000u) ? ~u : (u | 0x80000000u);
}

__global__ void topk_kernel() {
    int bl = blockIdx.x;            // 0..11
    int level = bl >> 2, b = bl & 3;
    int N, off;
    if (level == 0)      { N = N3; off = 0;       }
    else if (level == 1) { N = N4; off = N3;      }
    else                 { N = N5; off = N3 + N4; }
    const float* sc = g_scores + b*NTOT + off;

    __shared__ unsigned hist[4096];
    __shared__ unsigned long long cand[2048];
    __shared__ int sT, scnt;
    int tid = threadIdx.x;          // 1024

    for (int i = tid; i < 4096; i += 1024) hist[i] = 0;
    if (tid == 0) scnt = 0;
    __syncthreads();
    for (int i = tid; i < N; i += 1024)
        atomicAdd(&hist[f2o(sc[i]) >> 20], 1u);
    __syncthreads();
    if (tid == 0) {
        unsigned cum = 0; int T = 0;
        for (int bin = 4095; bin >= 0; bin--) {
            cum += hist[bin];
            if (cum >= PRE) { T = bin; break; }
        }
        sT = T;
    }
    __syncthreads();
    int T = sT;
    for (int i = tid; i < N; i += 1024) {
        unsigned u = f2o(sc[i]);
        if ((int)(u >> 20) >= T) {
            int p = atomicAdd(&scnt, 1);
            if (p < 2048)
                cand[p] = ((unsigned long long)u << 32) | (unsigned)(~i);
        }
    }
    __syncthreads();
    int cnt = min(scnt, 2048);
    for (int i = cnt + tid; i < 2048; i += 1024) cand[i] = 0ull;
    __syncthreads();

    // bitonic sort, descending (key = score-orderable<<32 | ~idx: ties -> lower idx)
    for (int k = 2; k <= 2048; k <<= 1) {
        for (int j = k >> 1; j > 0; j >>= 1) {
            for (int i = tid; i < 2048; i += 1024) {
                int ixj = i ^ j;
                if (ixj > i) {
                    bool desc = ((i & k) == 0);
                    unsigned long long a = cand[i], c = cand[ixj];
                    bool sw = desc ? (a < c) : (a > c);
                    if (sw) { cand[i] = c; cand[ixj] = a; }
                }
            }
            __syncthreads();
        }
    }

    if (tid < PRE) {
        unsigned idx = ~(unsigned)(cand[tid] & 0xFFFFFFFFu);
        int gi = b*NTOT + off + (int)idx;
        float4 bx = *(const float4*)(g_boxes + (size_t)gi*4);
        *(float4*)(g_tboxes + (size_t)(bl*PRE + tid)*4) = bx;
    }
}

// ---------------- sequential greedy NMS + emit ----------------
__global__ void nms_kernel(float* __restrict__ out) {
    int bl = blockIdx.x;
    int level = bl >> 2, b = bl & 3;
    __shared__ float bx[PRE][4];
    __shared__ float ar_[PRE];
    __shared__ int keep[PRE];
    __shared__ int ord[PRE];
    __shared__ int ktot;
    int tid = threadIdx.x;   // 512

    if (tid < PRE) {
        float4 v = *(const float4*)(g_tboxes + (size_t)(bl*PRE + tid)*4);
        bx[tid][0] = v.x; bx[tid][1] = v.y; bx[tid][2] = v.z; bx[tid][3] = v.w;
        ar_[tid] = (v.z - v.x) * (v.w - v.y);
        keep[tid] = 1;
    }
    __syncthreads();

    for (int i = 0; i < PRE; i++) {
        if (keep[i] && tid > i && tid < PRE && keep[tid]) {
            float xx1 = fmaxf(bx[i][0], bx[tid][0]);
            float yy1 = fmaxf(bx[i][1], bx[tid][1]);
            float xx2 = fminf(bx[i][2], bx[tid][2]);
            float yy2 = fminf(bx[i][3], bx[tid][3]);
            float w = fmaxf(xx2 - xx1, 0.f);
            float h = fmaxf(yy2 - yy1, 0.f);
            float inter = w * h;
            float uni = fmaxf(ar_[i] + ar_[tid] - inter, 1e-8f);
            if (inter / uni > NMS_T) keep[tid] = 0;
        }
        __syncthreads();
    }

    if (tid == 0) {
        int cnt = 0;
        for (int i = 0; i < PRE; i++) {
            if (keep[i] && cnt < POST) { ord[i] = cnt; cnt++; }
            else ord[i] = -1;
        }
        ktot = cnt;
    }
    __syncthreads();

    float* obase = out + (size_t)(b*300 + level*100)*4;
    if (tid < PRE && ord[tid] >= 0)
        *(float4*)(obase + (size_t)ord[tid]*4) =
            make_float4(bx[tid][0], bx[tid][1], bx[tid][2], bx[tid][3]);
    if (tid < POST && tid >= ktot)
        *(float4*)(obase + (size_t)tid*4) = make_float4(0.f, 0.f, 0.f, 0.f);
}

// ---------------- launcher ----------------
extern "C" void kernel_launch(void* const* d_in, const int* in_sizes, int n_in,
                              void* d_out, int out_size) {
    const float* f3   = (const float*)d_in[0];
    const float* f4   = (const float*)d_in[1];
    const float* f5   = (const float*)d_in[2];
    const float* wst  = (const float*)d_in[3];
    const float* bst  = (const float*)d_in[4];
    const float* wobj = (const float*)d_in[5];
    const float* bobj = (const float*)d_in[6];
    const float* wbox = (const float*)d_in[7];
    const float* bbox = (const float*)d_in[8];
    float* out = (float*)d_out;
    (void)in_sizes; (void)n_in; (void)out_size;

    cudaFuncSetAttribute(conv_head_kernel,
                         cudaFuncAttributeMaxDynamicSharedMemorySize, CONV_SMEM);

    prep_stem_w<<<(9*256*256 + 255)/256, 256>>>(wst);
    prep_head<<<16, 256>>>(wobj, bobj, wbox, bbox);
    conv_head_kernel<<<1344, 256, CONV_SMEM>>>(f3, f4, f5, bst);
    topk_kernel<<<12, 1024>>>();
    nms_kernel<<<12, 512>>>(out);
}

// round 11
// speedup vs baseline: 1.0668x; 1.0668x over previous
#include <cuda_runtime.h>
#include <math.h>
#include <stdint.h>

// ---------------- problem constants (fixed for this instance) ----------------
static constexpr int Bn  = 4;
static constexpr int C   = 256;
static constexpr int S3  = 128, S4 = 64, S5 = 32;
static constexpr int N3  = S3*S3*3;          // 49152
static constexpr int N4  = S4*S4*3;          // 12288
static constexpr int N5  = S5*S5*3;          // 3072
static constexpr int NTOT = N3 + N4 + N5;    // 64512
static constexpr int PRE  = 400;
static constexpr int POST = 100;
static constexpr float NMS_T  = 0.7f;
static constexpr float IMGW   = 1024.0f;
static constexpr float IMGH   = 1024.0f;
#define SCLAMP 3.3322045101752038f

// ---------------- device scratch (keep small: large globals trip the mem guard) ----------------
__device__ float g_wt[9*256*256];     // [pos][cin][cout]
__device__ float g_wh[16*256];        // head weights: rows 0..2 obj, 3..14 box, 15 zero
__device__ float g_bh[16];
__device__ float g_scores[Bn*NTOT];
__device__ float g_boxes [Bn*NTOT*4];
__device__ float g_tboxes[12*PRE*4];  // top-400 boxes per (level,b)

// packed fp32x2 FMA (Blackwell FFMA2; exact IEEE per lane)
#define FMA2(ACC, S, B) \
    asm("fma.rn.f32x2 %0, %1, %2, %0;" : "+l"(ACC) : "l"(S), "l"(B))
#define SPLAT2(D, V) \
    asm("mov.b64 %0, {%1, %1};" : "=l"(D) : "r"(__float_as_uint(V)))

// ---------------- weight prep ----------------
__global__ void prep_stem_w(const float* __restrict__ w) {
    int i = blockIdx.x * 256 + threadIdx.x;
    if (i < 9*256*256) {
        int pos  = i >> 16;          // /65536
        int cin  = (i >> 8) & 255;
        int cout = i & 255;
        g_wt[i] = w[(cout*256 + cin)*9 + pos];
    }
}

__global__ void prep_head(const float* __restrict__ wobj, const float* __restrict__ bobj,
                          const float* __restrict__ wbox, const float* __restrict__ bbox) {
    int i = blockIdx.x * 256 + threadIdx.x;
    if (i < 16*256) {
        int o = i >> 8, k = i & 255;
        float v = 0.f;
        if (o < 3)        v = wobj[o*256 + k];
        else if (o < 15)  v = wbox[(o-3)*256 + k];
        g_wh[i] = v;
    }
    if (i < 16) {
        float v = 0.f;
        if (i < 3)        v = bobj[i];
        else if (i < 15)  v = bbox[i-3];
        g_bh[i] = v;
    }
}

// ---------------- fused stem conv + head + decode ----------------
// tile: M=256 couts x N=64 pixels, 256 threads, thread tile 8x8 (packed as 8x4 f32x2).
// K loop: 9 positions x 32 chunks of 8 cins = 288 steps, double-buffered smem.
static constexpr int CONV_SMEM = (256*65 + 16*256 + 16*65) * 4;  // 87104 B (epilogue is the max)

__global__ __launch_bounds__(256, 2)
void conv_head_kernel(const float* __restrict__ f3, const float* __restrict__ f4,
                      const float* __restrict__ f5, const float* __restrict__ bstem) {
    extern __shared__ float sm[];
    float* As = sm;                 // [2][8][256]
    float* Bs = sm + 2*8*256;       // [2][8][64]
    float* st = sm;                 // epilogue alias: stem [256][65]
    float* wh = sm + 256*65;        //                 head w [16][256]
    float* hs = sm + 256*65 + 16*256; //               head out [16][65]

    int t = blockIdx.x;
    int level, b, tile, S, logS, stride, loff;
    const float* feat;
    if (t < 1024)      { level=0; b=t>>8; tile=t&255; S=128; logS=7; stride=8;  feat=f3; loff=0;      }
    else if (t < 1280) { t-=1024; level=1; b=t>>6; tile=t&63; S=64;  logS=6; stride=16; feat=f4; loff=N3;     }
    else               { t-=1280; level=2; b=t>>4; tile=t&15; S=32;  logS=5; stride=32; feat=f5; loff=N3+N4;  }
    (void)level;

    const int tid = threadIdx.x;
    const int m0  = (tid >> 3) * 8;
    const int n0  = (tid & 7) * 8;
    const int p0  = tile * 64;
    const int nb  = tid & 63;        // B-tile pixel this thread loads
    const int kb0 = tid >> 6;        // 0..3
    const int pix = p0 + nb;
    const int ph  = pix >> logS;
    const int pw  = pix & (S - 1);
    const int SS2 = logS + logS;

    // packed accumulators: [cout i][pixel pair jp], pair = (n0+2jp, n0+2jp+1)
    unsigned long long acc2[8][4];
    #pragma unroll
    for (int i = 0; i < 8; i++)
        #pragma unroll
        for (int j = 0; j < 4; j++) acc2[i][j] = 0ull;

    float ra[8], rb[2];
    auto load_step = [&](int s) {
        int pos = s >> 5;
        int c0  = (s & 31) << 3;
        const float* wrow = g_wt + (pos << 16) + (c0 << 8) + tid;
        #pragma unroll
        for (int i = 0; i < 8; i++) ra[i] = wrow[i << 8];
        int kh = pos / 3;
        int dh = kh - 1, dw = pos - kh*3 - 1;
        int y = ph + dh, x = pw + dw;
        rb[0] = 0.f; rb[1] = 0.f;
        if ((unsigned)y < (unsigned)S && (unsigned)x < (unsigned)S) {
            const float* fb = feat + (((b << 8) + c0 + kb0) << SS2) + (y << logS) + x;
            rb[0] = fb[0];
            rb[1] = fb[4 << SS2];
        }
    };

    load_step(0);
    for (int s = 0; s < 288; s++) {
        int buf = s & 1;
        __syncthreads();
        {
            float* Aw = As + buf*8*256;
            float* Bw = Bs + buf*8*64;
            #pragma unroll
            for (int i = 0; i < 8; i++) Aw[i*256 + tid] = ra[i];
            Bw[kb0*64 + nb]     = rb[0];
            Bw[(kb0+4)*64 + nb] = rb[1];
        }
        __syncthreads();
        if (s + 1 < 288) load_step(s + 1);
        const float* Ak = As + buf*8*256;
        const float* Bk = Bs + buf*8*64;
        #pragma unroll
        for (int k = 0; k < 8; k++) {
            // A: 8 couts contiguous -> 2x LDS.128 ; B: 4 pixel pairs -> 4x LDS.64
            const float4 a0 = *(const float4*)(Ak + k*256 + m0);
            const float4 a1 = *(const float4*)(Ak + k*256 + m0 + 4);
            unsigned long long b2[4];
            #pragma unroll
            for (int j = 0; j < 4; j++)
                b2[j] = *(const unsigned long long*)(Bk + k*64 + n0 + 2*j);
            const float av[8] = {a0.x, a0.y, a0.z, a0.w, a1.x, a1.y, a1.z, a1.w};
            #pragma unroll
            for (int i = 0; i < 8; i++) {
                unsigned long long sp;
                SPLAT2(sp, av[i]);
                FMA2(acc2[i][0], sp, b2[0]);
                FMA2(acc2[i][1], sp, b2[1]);
                FMA2(acc2[i][2], sp, b2[2]);
                FMA2(acc2[i][3], sp, b2[3]);
            }
        }
    }
    __syncthreads();   // done with As/Bs; smem re-used below

    // bias + relu, stash stem tile
    #pragma unroll
    for (int i = 0; i < 8; i++) {
        float bsv = bstem[m0 + i];
        #pragma unroll
        for (int j = 0; j < 4; j++) {
            unsigned u0, u1;
            asm("mov.b64 {%0, %1}, %2;" : "=r"(u0), "=r"(u1) : "l"(acc2[i][j]));
            st[(m0 + i)*65 + (n0 + 2*j)]     = fmaxf(__uint_as_float(u0) + bsv, 0.f);
            st[(m0 + i)*65 + (n0 + 2*j + 1)] = fmaxf(__uint_as_float(u1) + bsv, 0.f);
        }
    }
    for (int i = tid; i < 16*256; i += 256) wh[i] = g_wh[i];
    __syncthreads();

    // head GEMM: 15(+1 pad) x 64 from smem
    {
        int og = tid >> 6;       // 0..3 -> head rows og*4..og*4+3
        int n  = tid & 63;
        float h0 = 0.f, h1 = 0.f, h2 = 0.f, h3 = 0.f;
        const float* w0 = wh + (og*4 + 0)*256;
        const float* w1 = wh + (og*4 + 1)*256;
        const float* w2 = wh + (og*4 + 2)*256;
        const float* w3 = wh + (og*4 + 3)*256;
        #pragma unroll 4
        for (int k = 0; k < 256; k++) {
            float sv = st[k*65 + n];
            h0 = fmaf(w0[k], sv, h0);
            h1 = fmaf(w1[k], sv, h1);
            h2 = fmaf(w2[k], sv, h2);
            h3 = fmaf(w3[k], sv, h3);
        }
        hs[(og*4 + 0)*65 + n] = h0 + g_bh[og*4 + 0];
        hs[(og*4 + 1)*65 + n] = h1 + g_bh[og*4 + 1];
        hs[(og*4 + 2)*65 + n] = h2 + g_bh[og*4 + 2];
        hs[(og*4 + 3)*65 + n] = h3 + g_bh[og*4 + 3];
    }
    __syncthreads();

    // decode anchors + deltas, clip, write scores/boxes
    if (tid < 192) {
        int n = tid / 3;
        int a = tid - n*3;
        int pixel = p0 + n;
        int hh = pixel >> logS, ww = pixel & (S - 1);
        float sF   = (float)stride;
        float side = 8.0f * sF;
        float area = side * side;
        float arat = (a == 0) ? 0.5f : (a == 1 ? 1.0f : 2.0f);
        float wsz  = sqrtf(area / arat);
        float hsz  = area / wsz;
        float xc = (ww + 0.5f) * sF, yc = (hh + 0.5f) * sF;
        float x1 = xc - wsz*0.5f, x2 = xc + wsz*0.5f;
        float y1 = yc - hsz*0.5f, y2 = yc + hsz*0.5f;
        float aw = x2 - x1, ah = y2 - y1;
        float acx = x1 + 0.5f*aw, acy = y1 + 0.5f*ah;

        float dx = hs[(3 + a*4 + 0)*65 + n];
        float dy = hs[(3 + a*4 + 1)*65 + n];
        float dw = fminf(hs[(3 + a*4 + 2)*65 + n], SCLAMP);
        float dh = fminf(hs[(3 + a*4 + 3)*65 + n], SCLAMP);
        float pcx = dx*aw + acx, pcy = dy*ah + acy;
        float pwd = expf(dw)*aw, phd = expf(dh)*ah;
        float bx1 = fminf(fmaxf(pcx - 0.5f*pwd, 0.f), IMGW);
        float by1 = fminf(fmaxf(pcy - 0.5f*phd, 0.f), IMGH);
        float bx2 = fminf(fmaxf(pcx + 0.5f*pwd, 0.f), IMGW);
        float by2 = fminf(fmaxf(pcy + 0.5f*phd, 0.f), IMGH);

        int gi = b*NTOT + loff + pixel*3 + a;
        g_scores[gi] = hs[a*65 + n];
        *(float4*)(g_boxes + (size_t)gi*4) = make_float4(bx1, by1, bx2, by2);
    }
}

// ---------------- top-400 per (level,b): radix histogram + bitonic ----------------
__device__ __forceinline__ unsigned f2o(float f) {
    unsigned u = __float_as_uint(f);
    return (u & 0x80000000u) ? ~u : (u | 0x80000000u);
}

__global__ void topk_kernel() {
    int bl = blockIdx.x;            // 0..11
    int level = bl >> 2, b = bl & 3;
    int N, off;
    if (level == 0)      { N = N3; off = 0;       }
    else if (level == 1) { N = N4; off = N3;      }
    else                 { N = N5; off = N3 + N4; }
    const float* sc = g_scores + b*NTOT + off;

    __shared__ unsigned hist[4096];
    __shared__ unsigned long long cand[2048];
    __shared__ int sT, scnt;
    int tid = threadIdx.x;          // 1024

    for (int i = tid; i < 4096; i += 1024) hist[i] = 0;
    if (tid == 0) scnt = 0;
    __syncthreads();
    for (int i = tid; i < N; i += 1024)
        atomicAdd(&hist[f2o(sc[i]) >> 20], 1u);
    __syncthreads();
    if (tid == 0) {
        unsigned cum = 0; int T = 0;
        for (int bin = 4095; bin >= 0; bin--) {
            cum += hist[bin];
            if (cum >= PRE) { T = bin; break; }
        }
        sT = T;
    }
    __syncthreads();
    int T = sT;
    for (int i = tid; i < N; i += 1024) {
        unsigned u = f2o(sc[i]);
        if ((int)(u >> 20) >= T) {
            int p = atomicAdd(&scnt, 1);
            if (p < 2048)
                cand[p] = ((unsigned long long)u << 32) | (unsigned)(~i);
        }
    }
    __syncthreads();
    int cnt = min(scnt, 2048);
    for (int i = cnt + tid; i < 2048; i += 1024) cand[i] = 0ull;
    __syncthreads();

    // bitonic sort, descending (key = score-orderable<<32 | ~idx: ties -> lower idx)
    for (int k = 2; k <= 2048; k <<= 1) {
        for (int j = k >> 1; j > 0; j >>= 1) {
            for (int i = tid; i < 2048; i += 1024) {
                int ixj = i ^ j;
                if (ixj > i) {
                    bool desc = ((i & k) == 0);
                    unsigned long long a = cand[i], c = cand[ixj];
                    bool sw = desc ? (a < c) : (a > c);
                    if (sw) { cand[i] = c; cand[ixj] = a; }
                }
            }
            __syncthreads();
        }
    }

    if (tid < PRE) {
        unsigned idx = ~(unsigned)(cand[tid] & 0xFFFFFFFFu);
        int gi = b*NTOT + off + (int)idx;
        float4 bx = *(const float4*)(g_boxes + (size_t)gi*4);
        *(float4*)(g_tboxes + (size_t)(bl*PRE + tid)*4) = bx;
    }
}

// ---------------- sequential greedy NMS + emit ----------------
__global__ void nms_kernel(float* __restrict__ out) {
    int bl = blockIdx.x;
    int level = bl >> 2, b = bl & 3;
    __shared__ float bx[PRE][4];
    __shared__ float ar_[PRE];
    __shared__ int keep[PRE];
    __shared__ int ord[PRE];
    __shared__ int ktot;
    int tid = threadIdx.x;   // 512

    if (tid < PRE) {
        float4 v = *(const float4*)(g_tboxes + (size_t)(bl*PRE + tid)*4);
        bx[tid][0] = v.x; bx[tid][1] = v.y; bx[tid][2] = v.z; bx[tid][3] = v.w;
        ar_[tid] = (v.z - v.x) * (v.w - v.y);
        keep[tid] = 1;
    }
    __syncthreads();

    for (int i = 0; i < PRE; i++) {
        if (keep[i] && tid > i && tid < PRE && keep[tid]) {
            float xx1 = fmaxf(bx[i][0], bx[tid][0]);
            float yy1 = fmaxf(bx[i][1], bx[tid][1]);
            float xx2 = fminf(bx[i][2], bx[tid][2]);
            float yy2 = fminf(bx[i][3], bx[tid][3]);
            float w = fmaxf(xx2 - xx1, 0.f);
            float h = fmaxf(yy2 - yy1, 0.f);
            float inter = w * h;
            float uni = fmaxf(ar_[i] + ar_[tid] - inter, 1e-8f);
            if (inter / uni > NMS_T) keep[tid] = 0;
        }
        __syncthreads();
    }

    if (tid == 0) {
        int cnt = 0;
        for (int i = 0; i < PRE; i++) {
            if (keep[i] && cnt < POST) { ord[i] = cnt; cnt++; }
            else ord[i] = -1;
        }
        ktot = cnt;
    }
    __syncthreads();

    float* obase = out + (size_t)(b*300 + level*100)*4;
    if (tid < PRE && ord[tid] >= 0)
        *(float4*)(obase + (size_t)ord[tid]*4) =
            make_float4(bx[tid][0], bx[tid][1], bx[tid][2], bx[tid][3]);
    if (tid < POST && tid >= ktot)
        *(float4*)(obase + (size_t)tid*4) = make_float4(0.f, 0.f, 0.f, 0.f);
}

// ---------------- launcher ----------------
extern "C" void kernel_launch(void* const* d_in, const int* in_sizes, int n_in,
                              void* d_out, int out_size) {
    const float* f3   = (const float*)d_in[0];
    const float* f4   = (const float*)d_in[1];
    const float* f5   = (const float*)d_in[2];
    const float* wst  = (const float*)d_in[3];
    const float* bst  = (const float*)d_in[4];
    const float* wobj = (const float*)d_in[5];
    const float* bobj = (const float*)d_in[6];
    const float* wbox = (const float*)d_in[7];
    const float* bbox = (const float*)d_in[8];
    float* out = (float*)d_out;
    (void)in_sizes; (void)n_in; (void)out_size;

    cudaFuncSetAttribute(conv_head_kernel,
                         cudaFuncAttributeMaxDynamicSharedMemorySize, CONV_SMEM);

    prep_stem_w<<<(9*256*256 + 255)/256, 256>>>(wst);
    prep_head<<<16, 256>>>(wobj, bobj, wbox, bbox);
    conv_head_kernel<<<1344, 256, CONV_SMEM>>>(f3, f4, f5, bst);
    topk_kernel<<<12, 1024>>>();
    nms_kernel<<<12, 512>>>(out);
}